// round 9
// baseline (speedup 1.0000x reference)
#include <cuda_runtime.h>
#include <cuda_bf16.h>
#include <cstdint>

#define N_NODES 50000
#define N_EDGES 625000
#define C 128
#define NPART ((N_NODES + 255) / 256)   // 196 scan blocks
#define GM 64                            // GEMM rows per block
#define GBLKS ((N_NODES + GM - 1) / GM)  // 782
#define PADROWS (GBLKS * GM)             // 50048

// Scratch (__device__ globals; allocations are banned)
__device__ __align__(16) float  g_y[(size_t)PADROWS * C];  // x @ W^T (row-padded)
__device__ __align__(16) float2 g_Wp[C * C];  // [k][n] -> (tf32 hi, tf32 lo) of W[n][k]
__device__ float g_dis[N_NODES];             // deg^-1/2
__device__ int   g_row[N_EDGES];
__device__ int   g_col[N_EDGES];
__device__ int   g_cnt[N_NODES];             // degree counts
__device__ int   g_cur[N_NODES];             // fill cursors
__device__ int   g_off[N_NODES + 1];         // CSR offsets
__device__ int   g_ecol[N_EDGES];            // CSR column (src) ids
__device__ int   g_part[NPART];              // scan partials
__device__ int   g_is64;

// ---------------------------------------------------------------------------
static __device__ __forceinline__ uint32_t tf32r(float v) {
    uint32_t r;
    asm("cvt.rna.tf32.f32 %0, %1;" : "=r"(r) : "f"(v));
    return r;
}

static __device__ __forceinline__ void mma8(float4& d, const uint32_t* a,
                                            uint32_t b0, uint32_t b1) {
    asm volatile(
        "mma.sync.aligned.m16n8k8.row.col.f32.tf32.tf32.f32 "
        "{%0,%1,%2,%3}, {%4,%5,%6,%7}, {%8,%9}, {%0,%1,%2,%3};"
        : "+f"(d.x), "+f"(d.y), "+f"(d.z), "+f"(d.w)
        : "r"(a[0]), "r"(a[1]), "r"(a[2]), "r"(a[3]), "r"(b0), "r"(b1));
}

// ---------------------------------------------------------------------------
// Fused: dtype detect (block 0) + zero counters + W hi/lo split+transpose
__global__ void k_detect_prep(const long long* __restrict__ ei,
                              const float* __restrict__ W) {
    int i = blockIdx.x * blockDim.x + threadIdx.x;
    if (i < N_NODES) { g_cnt[i] = 0; g_cur[i] = 0; }
    if (i < C * C) {
        int n = i >> 7, k = i & 127;
        float w = W[i];
        uint32_t h = tf32r(w);
        float hi = __uint_as_float(h);
        float lo = __uint_as_float(tf32r(w - hi));
        g_Wp[k * C + n] = make_float2(hi, lo);
    }
    if (blockIdx.x == 0) {
        __shared__ int ok;
        if (threadIdx.x == 0) ok = 1;
        __syncthreads();
        for (int s = threadIdx.x; s < 1024; s += blockDim.x) {
            long long v = ei[s];
            if (v < 0 || v >= N_NODES) atomicExch(&ok, 0);
        }
        __syncthreads();
        if (threadIdx.x == 0) g_is64 = ok;
    }
}

// normalize edges + count degrees in one pass
__global__ void k_edges(const void* __restrict__ ei) {
    int e = blockIdx.x * blockDim.x + threadIdx.x;
    if (e >= N_EDGES) return;
    int r, c;
    if (g_is64) {
        const long long* p = (const long long*)ei;
        r = (int)p[e];
        c = (int)p[e + N_EDGES];
    } else {
        const int* p = (const int*)ei;
        r = p[e];
        c = p[e + N_EDGES];
    }
    g_row[e] = r;
    g_col[e] = c;
    if ((unsigned)r < N_NODES) atomicAdd(&g_cnt[r], 1);
}

// ---------------------------------------------------------------------------
__global__ void __launch_bounds__(256) k_scan1() {
    __shared__ int s[256];
    const int t = threadIdx.x;
    const int i = blockIdx.x * 256 + t;
    s[t] = (i < N_NODES) ? g_cnt[i] : 0;
    __syncthreads();
#pragma unroll
    for (int off = 128; off > 0; off >>= 1) {
        if (t < off) s[t] += s[t + off];
        __syncthreads();
    }
    if (t == 0) g_part[blockIdx.x] = s[0];
}

__global__ void __launch_bounds__(256) k_scan_off() {
    __shared__ int sp[256];
    __shared__ int s[256];
    const int t = threadIdx.x;

    const int pv = (t < NPART) ? g_part[t] : 0;
    sp[t] = pv;
    __syncthreads();
#pragma unroll
    for (int off = 1; off < 256; off <<= 1) {
        int u = (t >= off) ? sp[t - off] : 0;
        __syncthreads();
        sp[t] += u;
        __syncthreads();
    }
    const int blk_prefix = (blockIdx.x == 0) ? 0 : sp[blockIdx.x - 1];
    if (blockIdx.x == 0 && t == 0) g_off[N_NODES] = sp[NPART - 1];

    const int i = blockIdx.x * 256 + t;
    const int v = (i < N_NODES) ? g_cnt[i] : 0;
    s[t] = v;
    __syncthreads();
#pragma unroll
    for (int off = 1; off < 256; off <<= 1) {
        int u = (t >= off) ? s[t - off] : 0;
        __syncthreads();
        s[t] += u;
        __syncthreads();
    }
    if (i < N_NODES) {
        g_off[i] = s[t] - v + blk_prefix;
        g_dis[i] = (v > 0) ? rsqrtf((float)v) : 0.f;
    }
}

__global__ void k_fill_csr() {
    int e = blockIdx.x * blockDim.x + threadIdx.x;
    if (e >= N_EDGES) return;
    unsigned r = (unsigned)g_row[e];
    unsigned c = (unsigned)g_col[e];
    if (r >= N_NODES || c >= N_NODES) return;
    int pos = g_off[r] + atomicAdd(&g_cur[r], 1);
    g_ecol[pos] = (int)c;
}

// ---------------------------------------------------------------------------
// y = x @ W^T via mma.sync m16n8k8 3xTF32 (tensor pipe; no tcgen05 on this
// toolchain's compute_103 virtual arch).
// Block: 4 warps, M=64 (16 rows/warp), N=128, K in 16 chunks of 8.
__global__ void __launch_bounds__(128) k_gemm_mma(const float* __restrict__ x) {
    __shared__ float  xs[GM][132];    // pad 132: A-frag LDS conflict-free
    __shared__ float2 wc[8][132];     // k-chunk of W hi/lo, [kk][n]

    const int tid = threadIdx.x;
    const int wid = tid >> 5, lane = tid & 31;
    const int g = lane >> 2, t = lane & 3;
    const int row0 = blockIdx.x * GM;

    // Load x tile (coalesced float4; zero-pad tail rows)
    for (int i = tid; i < GM * 32; i += 128) {
        int r = i >> 5, q = i & 31;
        float4 v = make_float4(0.f, 0.f, 0.f, 0.f);
        if (row0 + r < N_NODES)
            v = ((const float4*)(x + (size_t)(row0 + r) * C))[q];
        *(float4*)&xs[r][4 * q] = v;
    }

    const int r0 = wid * 16 + g;
    const int r1 = r0 + 8;

    float4 acc[16];
#pragma unroll
    for (int nt = 0; nt < 16; nt++) acc[nt] = make_float4(0.f, 0.f, 0.f, 0.f);

    for (int kc = 0; kc < 16; kc++) {
        __syncthreads();   // wc reuse guard (also covers xs on first iter)
        // Stage W chunk: rows k=8kc..8kc+7, 128 float2 each (coalesced)
        for (int i = tid; i < 8 * 64; i += 128) {
            int kk = i >> 6, j = i & 63;
            float4 v = *(const float4*)&g_Wp[(kc * 8 + kk) * C + j * 2];
            *(float4*)&wc[kk][j * 2] = v;
        }
        __syncthreads();

        const int k0 = kc * 8;
        // A fragments (hi/lo)
        uint32_t ah[4], al[4];
        {
            float v0 = xs[r0][k0 + t];
            float v1 = xs[r1][k0 + t];
            float v2 = xs[r0][k0 + t + 4];
            float v3 = xs[r1][k0 + t + 4];
            ah[0] = tf32r(v0); al[0] = tf32r(v0 - __uint_as_float(ah[0]));
            ah[1] = tf32r(v1); al[1] = tf32r(v1 - __uint_as_float(ah[1]));
            ah[2] = tf32r(v2); al[2] = tf32r(v2 - __uint_as_float(ah[2]));
            ah[3] = tf32r(v3); al[3] = tf32r(v3 - __uint_as_float(ah[3]));
        }
#pragma unroll
        for (int nt = 0; nt < 16; nt++) {
            const int n = nt * 8 + g;
            float2 p0 = wc[t][n];        // (hi,lo) of W[n][k0+t]
            float2 p1 = wc[t + 4][n];    // (hi,lo) of W[n][k0+t+4]
            uint32_t bh0 = __float_as_uint(p0.x), bl0 = __float_as_uint(p0.y);
            uint32_t bh1 = __float_as_uint(p1.x), bl1 = __float_as_uint(p1.y);
            mma8(acc[nt], ah, bh0, bh1);   // hi*hi
            mma8(acc[nt], ah, bl0, bl1);   // hi*lo
            mma8(acc[nt], al, bh0, bh1);   // lo*hi
        }
    }

    // Epilogue: D frag c0/c1 -> (row g, cols 2t,2t+1), c2/c3 -> row g+8
    const size_t gr0 = (size_t)(row0 + r0) * C;
    const size_t gr1 = (size_t)(row0 + r1) * C;
#pragma unroll
    for (int nt = 0; nt < 16; nt++) {
        const int cb = nt * 8 + 2 * t;
        *(float2*)&g_y[gr0 + cb] = make_float2(acc[nt].x, acc[nt].y);
        *(float2*)&g_y[gr1 + cb] = make_float2(acc[nt].z, acc[nt].w);
    }
}

// ---------------------------------------------------------------------------
// Warp per node: out[n] = b + dis[n] * sum_e dis[col_e] * y[col_e]
__global__ void __launch_bounds__(256) k_gather(float* __restrict__ out,
                                                const float* __restrict__ b) {
    int gtid = blockIdx.x * blockDim.x + threadIdx.x;
    int n = gtid >> 5;
    int lane = gtid & 31;
    if (n >= N_NODES) return;

    const float4 bias = __ldg(((const float4*)b) + lane);
    float ax = 0.f, ay = 0.f, az = 0.f, aw = 0.f;

    const int start = g_off[n];
    const int end = g_off[n + 1];
    const float dn = g_dis[n];

    for (int e = start; e < end; e++) {
        int c = g_ecol[e];
        float norm = dn * g_dis[c];
        float4 v = __ldg(((const float4*)(g_y + (size_t)c * C)) + lane);
        ax += norm * v.x;
        ay += norm * v.y;
        az += norm * v.z;
        aw += norm * v.w;
    }

    ((float4*)(out + (size_t)n * C))[lane] =
        make_float4(bias.x + ax, bias.y + ay, bias.z + az, bias.w + aw);
}

// ---------------------------------------------------------------------------
extern "C" void kernel_launch(void* const* d_in, const int* in_sizes, int n_in,
                              void* d_out, int out_size) {
    const float* x = (const float*)d_in[0];
    const void*  ei = d_in[1];
    const float* W = (const float*)d_in[2];
    const float* b = (const float*)d_in[3];
    float* out = (float*)d_out;

    k_detect_prep<<<(N_NODES + 255) / 256, 256>>>((const long long*)ei, W); // 1
    k_edges<<<(N_EDGES + 255) / 256, 256>>>(ei);                            // 2
    k_scan1<<<NPART, 256>>>();                                              // 3
    k_gemm_mma<<<GBLKS, 128>>>(x);                                          // 4 (profiled)
    k_scan_off<<<NPART, 256>>>();                                           // 5
    k_fill_csr<<<(N_EDGES + 255) / 256, 256>>>();                           // 6
    const long long total = (long long)N_NODES * 32;
    k_gather<<<(int)((total + 255) / 256), 256>>>(out, b);                  // 7
}

// round 10
// speedup vs baseline: 1.3656x; 1.3656x over previous
#include <cuda_runtime.h>
#include <cuda_bf16.h>
#include <cstdint>

#define N_NODES 50000
#define N_EDGES 625000
#define C 128
#define NPART ((N_NODES + 255) / 256)   // 196 scan blocks
#define GM 64                            // GEMM rows per block
#define GBLKS ((N_NODES + GM - 1) / GM)  // 782
#define PADROWS (GBLKS * GM)             // 50048
#define NFRAG (16 * 16 * 32)             // kc * nt * lane = 8192

// Scratch (__device__ globals; allocations are banned)
__device__ __align__(16) float  g_y[(size_t)PADROWS * C];  // x @ W^T (row-padded)
__device__ __align__(16) float4 g_Wf[NFRAG];  // pre-packed B frags (hi0,hi1,lo0,lo1)
__device__ float g_dis[N_NODES];             // deg^-1/2
__device__ int   g_row[N_EDGES];
__device__ int   g_col[N_EDGES];
__device__ int   g_cnt[N_NODES];             // degree counts
__device__ int   g_cur[N_NODES];             // fill cursors
__device__ int   g_off[N_NODES + 1];         // CSR offsets
__device__ int   g_ecol[N_EDGES];            // CSR column (src) ids
__device__ int   g_part[NPART];              // scan partials
__device__ int   g_is64;

// ---------------------------------------------------------------------------
static __device__ __forceinline__ uint32_t tf32r(float v) {
    uint32_t r;
    asm("cvt.rna.tf32.f32 %0, %1;" : "=r"(r) : "f"(v));
    return r;
}

static __device__ __forceinline__ void mma8(float4& d, const uint32_t* a,
                                            uint32_t b0, uint32_t b1) {
    asm volatile(
        "mma.sync.aligned.m16n8k8.row.col.f32.tf32.tf32.f32 "
        "{%0,%1,%2,%3}, {%4,%5,%6,%7}, {%8,%9}, {%0,%1,%2,%3};"
        : "+f"(d.x), "+f"(d.y), "+f"(d.z), "+f"(d.w)
        : "r"(a[0]), "r"(a[1]), "r"(a[2]), "r"(a[3]), "r"(b0), "r"(b1));
}

// ---------------------------------------------------------------------------
// Fused: dtype detect (block 0) + zero counters + B-fragment pack of W.
// Frag layout matches mma.m16n8k8 B operand: lane -> n = nt*8 + lane/4,
// k = kc*8 + lane%4; float4 = (hi W[n][k], hi W[n][k+4], lo..., lo...).
__global__ void k_detect_prep(const long long* __restrict__ ei,
                              const float* __restrict__ W) {
    int i = blockIdx.x * blockDim.x + threadIdx.x;
    if (i < N_NODES) { g_cnt[i] = 0; g_cur[i] = 0; }
    if (i < NFRAG) {
        int lane = i & 31;
        int frag = i >> 5;
        int nt = frag & 15;
        int kc = frag >> 4;
        int n = nt * 8 + (lane >> 2);
        int k = kc * 8 + (lane & 3);
        float w0 = W[n * C + k];
        float w1 = W[n * C + k + 4];
        float h0 = __uint_as_float(tf32r(w0));
        float h1 = __uint_as_float(tf32r(w1));
        float l0 = __uint_as_float(tf32r(w0 - h0));
        float l1 = __uint_as_float(tf32r(w1 - h1));
        g_Wf[i] = make_float4(h0, h1, l0, l1);
    }
    if (blockIdx.x == 0) {
        __shared__ int ok;
        if (threadIdx.x == 0) ok = 1;
        __syncthreads();
        for (int s = threadIdx.x; s < 1024; s += blockDim.x) {
            long long v = ei[s];
            if (v < 0 || v >= N_NODES) atomicExch(&ok, 0);
        }
        __syncthreads();
        if (threadIdx.x == 0) g_is64 = ok;
    }
}

// normalize edges + count degrees in one pass
__global__ void k_edges(const void* __restrict__ ei) {
    int e = blockIdx.x * blockDim.x + threadIdx.x;
    if (e >= N_EDGES) return;
    int r, c;
    if (g_is64) {
        const long long* p = (const long long*)ei;
        r = (int)p[e];
        c = (int)p[e + N_EDGES];
    } else {
        const int* p = (const int*)ei;
        r = p[e];
        c = p[e + N_EDGES];
    }
    g_row[e] = r;
    g_col[e] = c;
    if ((unsigned)r < N_NODES) atomicAdd(&g_cnt[r], 1);
}

// ---------------------------------------------------------------------------
__global__ void __launch_bounds__(256) k_scan1() {
    __shared__ int s[256];
    const int t = threadIdx.x;
    const int i = blockIdx.x * 256 + t;
    s[t] = (i < N_NODES) ? g_cnt[i] : 0;
    __syncthreads();
#pragma unroll
    for (int off = 128; off > 0; off >>= 1) {
        if (t < off) s[t] += s[t + off];
        __syncthreads();
    }
    if (t == 0) g_part[blockIdx.x] = s[0];
}

__global__ void __launch_bounds__(256) k_scan_off() {
    __shared__ int sp[256];
    __shared__ int s[256];
    const int t = threadIdx.x;

    const int pv = (t < NPART) ? g_part[t] : 0;
    sp[t] = pv;
    __syncthreads();
#pragma unroll
    for (int off = 1; off < 256; off <<= 1) {
        int u = (t >= off) ? sp[t - off] : 0;
        __syncthreads();
        sp[t] += u;
        __syncthreads();
    }
    const int blk_prefix = (blockIdx.x == 0) ? 0 : sp[blockIdx.x - 1];
    if (blockIdx.x == 0 && t == 0) g_off[N_NODES] = sp[NPART - 1];

    const int i = blockIdx.x * 256 + t;
    const int v = (i < N_NODES) ? g_cnt[i] : 0;
    s[t] = v;
    __syncthreads();
#pragma unroll
    for (int off = 1; off < 256; off <<= 1) {
        int u = (t >= off) ? s[t - off] : 0;
        __syncthreads();
        s[t] += u;
        __syncthreads();
    }
    if (i < N_NODES) {
        g_off[i] = s[t] - v + blk_prefix;
        g_dis[i] = (v > 0) ? rsqrtf((float)v) : 0.f;
    }
}

__global__ void k_fill_csr() {
    int e = blockIdx.x * blockDim.x + threadIdx.x;
    if (e >= N_EDGES) return;
    unsigned r = (unsigned)g_row[e];
    unsigned c = (unsigned)g_col[e];
    if (r >= N_NODES || c >= N_NODES) return;
    int pos = g_off[r] + atomicAdd(&g_cur[r], 1);
    g_ecol[pos] = (int)c;
}

// ---------------------------------------------------------------------------
// y = x @ W^T via mma.sync m16n8k8 3xTF32.
// 256 threads = 8 warps: mg = wid>>2 (2 m-tile pairs), ng = wid&3 (4 n-tiles).
// B frags pre-packed in g_Wf (L1-resident); ONE __syncthreads total.
__global__ void __launch_bounds__(256) k_gemm_mma(const float* __restrict__ x) {
    __shared__ float xs[GM][132];   // pad 132: A-frag LDS conflict-free

    const int tid = threadIdx.x;
    const int wid = tid >> 5, lane = tid & 31;
    const int g = lane >> 2, t = lane & 3;
    const int mg = wid >> 2;        // 0..1  -> rows mg*32 + mt*16
    const int ng = wid & 3;         // 0..3  -> nt = ng*4 + ntl
    const int row0 = blockIdx.x * GM;

    // Load x tile (coalesced float4; zero-pad tail rows)
    for (int i = tid; i < GM * 32; i += 256) {
        int r = i >> 5, q = i & 31;
        float4 v = make_float4(0.f, 0.f, 0.f, 0.f);
        if (row0 + r < N_NODES)
            v = ((const float4*)(x + (size_t)(row0 + r) * C))[q];
        *(float4*)&xs[r][4 * q] = v;
    }
    __syncthreads();

    float4 acc[2][4];
#pragma unroll
    for (int mt = 0; mt < 2; mt++)
#pragma unroll
        for (int n = 0; n < 4; n++) acc[mt][n] = make_float4(0.f, 0.f, 0.f, 0.f);

    const float4* wf = g_Wf + (size_t)(ng * 4) * 32 + lane;

    for (int kc = 0; kc < 16; kc++) {
        const int k0 = kc * 8;
        // A fragments for 2 m-tiles (hi/lo split on the fly)
        uint32_t ah[2][4], al[2][4];
#pragma unroll
        for (int mt = 0; mt < 2; mt++) {
            const int r0 = mg * 32 + mt * 16 + g;
            float v0 = xs[r0][k0 + t];
            float v1 = xs[r0 + 8][k0 + t];
            float v2 = xs[r0][k0 + t + 4];
            float v3 = xs[r0 + 8][k0 + t + 4];
            ah[mt][0] = tf32r(v0); al[mt][0] = tf32r(v0 - __uint_as_float(ah[mt][0]));
            ah[mt][1] = tf32r(v1); al[mt][1] = tf32r(v1 - __uint_as_float(ah[mt][1]));
            ah[mt][2] = tf32r(v2); al[mt][2] = tf32r(v2 - __uint_as_float(ah[mt][2]));
            ah[mt][3] = tf32r(v3); al[mt][3] = tf32r(v3 - __uint_as_float(ah[mt][3]));
        }
#pragma unroll
        for (int ntl = 0; ntl < 4; ntl++) {
            const float4 bf = __ldg(wf + (size_t)(kc * 16 + ntl) * 32);
            const uint32_t h0 = __float_as_uint(bf.x), h1 = __float_as_uint(bf.y);
            const uint32_t l0 = __float_as_uint(bf.z), l1 = __float_as_uint(bf.w);
#pragma unroll
            for (int mt = 0; mt < 2; mt++) {
                mma8(acc[mt][ntl], ah[mt], h0, h1);   // hi*hi
                mma8(acc[mt][ntl], ah[mt], l0, l1);   // hi*lo
                mma8(acc[mt][ntl], al[mt], h0, h1);   // lo*hi
            }
        }
    }

    // Epilogue: c0/c1 -> (row g, cols 2t,2t+1), c2/c3 -> row g+8
#pragma unroll
    for (int mt = 0; mt < 2; mt++) {
        const size_t gr0 = (size_t)(row0 + mg * 32 + mt * 16 + g) * C;
        const size_t gr1 = gr0 + 8 * C;
#pragma unroll
        for (int ntl = 0; ntl < 4; ntl++) {
            const int cb = (ng * 4 + ntl) * 8 + 2 * t;
            *(float2*)&g_y[gr0 + cb] = make_float2(acc[mt][ntl].x, acc[mt][ntl].y);
            *(float2*)&g_y[gr1 + cb] = make_float2(acc[mt][ntl].z, acc[mt][ntl].w);
        }
    }
}

// ---------------------------------------------------------------------------
// Warp per node: out[n] = b + dis[n] * sum_e dis[col_e] * y[col_e]
__global__ void __launch_bounds__(256) k_gather(float* __restrict__ out,
                                                const float* __restrict__ b) {
    int gtid = blockIdx.x * blockDim.x + threadIdx.x;
    int n = gtid >> 5;
    int lane = gtid & 31;
    if (n >= N_NODES) return;

    const float4 bias = __ldg(((const float4*)b) + lane);
    float ax = 0.f, ay = 0.f, az = 0.f, aw = 0.f;

    const int start = g_off[n];
    const int end = g_off[n + 1];
    const float dn = g_dis[n];

    for (int e = start; e < end; e++) {
        int c = g_ecol[e];
        float norm = dn * g_dis[c];
        float4 v = __ldg(((const float4*)(g_y + (size_t)c * C)) + lane);
        ax += norm * v.x;
        ay += norm * v.y;
        az += norm * v.z;
        aw += norm * v.w;
    }

    ((float4*)(out + (size_t)n * C))[lane] =
        make_float4(bias.x + ax, bias.y + ay, bias.z + az, bias.w + aw);
}

// ---------------------------------------------------------------------------
extern "C" void kernel_launch(void* const* d_in, const int* in_sizes, int n_in,
                              void* d_out, int out_size) {
    const float* x = (const float*)d_in[0];
    const void*  ei = d_in[1];
    const float* W = (const float*)d_in[2];
    const float* b = (const float*)d_in[3];
    float* out = (float*)d_out;

    k_detect_prep<<<(N_NODES + 255) / 256, 256>>>((const long long*)ei, W); // 1
    k_edges<<<(N_EDGES + 255) / 256, 256>>>(ei);                            // 2
    k_scan1<<<NPART, 256>>>();                                              // 3
    k_gemm_mma<<<GBLKS, 256>>>(x);                                          // 4 (profiled)
    k_scan_off<<<NPART, 256>>>();                                           // 5
    k_fill_csr<<<(N_EDGES + 255) / 256, 256>>>();                           // 6
    const long long total = (long long)N_NODES * 32;
    k_gather<<<(int)((total + 255) / 256), 256>>>(out, b);                  // 7
}

// round 11
// speedup vs baseline: 1.5361x; 1.1248x over previous
#include <cuda_runtime.h>
#include <cuda_bf16.h>
#include <cstdint>

#define N_NODES 50000
#define N_EDGES 625000
#define C 128
#define NPART ((N_NODES + 255) / 256)   // 196 scan blocks
#define GM 64                            // GEMM rows per block
#define GBLKS ((N_NODES + GM - 1) / GM)  // 782
#define PADROWS (GBLKS * GM)             // 50048
#define NFRAG (16 * 16 * 32)             // kc * nt * lane = 8192

// Scratch (__device__ globals; allocations are banned)
__device__ __align__(16) float  g_y[(size_t)PADROWS * C];  // x @ W^T (row-padded)
__device__ __align__(16) float4 g_Wf[NFRAG];  // pre-packed B frags (hi0,hi1,lo0,lo1)
__device__ float g_dis[N_NODES];             // deg^-1/2
__device__ int   g_row[N_EDGES];
__device__ int   g_col[N_EDGES];
__device__ int   g_cnt[N_NODES];             // degree counts
__device__ int   g_cur[N_NODES];             // fill cursors
__device__ int   g_off[N_NODES + 1];         // CSR offsets
__device__ int   g_ecol[N_EDGES];            // CSR column (src) ids
__device__ int   g_part[NPART];              // scan partials
__device__ int   g_is64;

// ---------------------------------------------------------------------------
static __device__ __forceinline__ uint32_t tf32r(float v) {
    uint32_t r;
    asm("cvt.rna.tf32.f32 %0, %1;" : "=r"(r) : "f"(v));
    return r;
}

static __device__ __forceinline__ void mma8(float4& d, const uint32_t* a,
                                            uint32_t b0, uint32_t b1) {
    asm volatile(
        "mma.sync.aligned.m16n8k8.row.col.f32.tf32.tf32.f32 "
        "{%0,%1,%2,%3}, {%4,%5,%6,%7}, {%8,%9}, {%0,%1,%2,%3};"
        : "+f"(d.x), "+f"(d.y), "+f"(d.z), "+f"(d.w)
        : "r"(a[0]), "r"(a[1]), "r"(a[2]), "r"(a[3]), "r"(b0), "r"(b1));
}

// ---------------------------------------------------------------------------
// Fused: dtype detect (block 0) + zero counters + B-fragment pack of W.
__global__ void k_detect_prep(const long long* __restrict__ ei,
                              const float* __restrict__ W) {
    int i = blockIdx.x * blockDim.x + threadIdx.x;
    if (i < N_NODES) { g_cnt[i] = 0; g_cur[i] = 0; }
    if (i < NFRAG) {
        int lane = i & 31;
        int frag = i >> 5;
        int nt = frag & 15;
        int kc = frag >> 4;
        int n = nt * 8 + (lane >> 2);
        int k = kc * 8 + (lane & 3);
        float w0 = W[n * C + k];
        float w1 = W[n * C + k + 4];
        float h0 = __uint_as_float(tf32r(w0));
        float h1 = __uint_as_float(tf32r(w1));
        float l0 = __uint_as_float(tf32r(w0 - h0));
        float l1 = __uint_as_float(tf32r(w1 - h1));
        g_Wf[i] = make_float4(h0, h1, l0, l1);
    }
    if (blockIdx.x == 0) {
        __shared__ int ok;
        if (threadIdx.x == 0) ok = 1;
        __syncthreads();
        for (int s = threadIdx.x; s < 1024; s += blockDim.x) {
            long long v = ei[s];
            if (v < 0 || v >= N_NODES) atomicExch(&ok, 0);
        }
        __syncthreads();
        if (threadIdx.x == 0) g_is64 = ok;
    }
}

// normalize edges + count degrees in one pass
__global__ void k_edges(const void* __restrict__ ei) {
    int e = blockIdx.x * blockDim.x + threadIdx.x;
    if (e >= N_EDGES) return;
    int r, c;
    if (g_is64) {
        const long long* p = (const long long*)ei;
        r = (int)p[e];
        c = (int)p[e + N_EDGES];
    } else {
        const int* p = (const int*)ei;
        r = p[e];
        c = p[e + N_EDGES];
    }
    g_row[e] = r;
    g_col[e] = c;
    if ((unsigned)r < N_NODES) atomicAdd(&g_cnt[r], 1);
}

// ---------------------------------------------------------------------------
__global__ void __launch_bounds__(256) k_scan1() {
    __shared__ int s[256];
    const int t = threadIdx.x;
    const int i = blockIdx.x * 256 + t;
    s[t] = (i < N_NODES) ? g_cnt[i] : 0;
    __syncthreads();
#pragma unroll
    for (int off = 128; off > 0; off >>= 1) {
        if (t < off) s[t] += s[t + off];
        __syncthreads();
    }
    if (t == 0) g_part[blockIdx.x] = s[0];
}

__global__ void __launch_bounds__(256) k_scan_off() {
    __shared__ int sp[256];
    __shared__ int s[256];
    const int t = threadIdx.x;

    const int pv = (t < NPART) ? g_part[t] : 0;
    sp[t] = pv;
    __syncthreads();
#pragma unroll
    for (int off = 1; off < 256; off <<= 1) {
        int u = (t >= off) ? sp[t - off] : 0;
        __syncthreads();
        sp[t] += u;
        __syncthreads();
    }
    const int blk_prefix = (blockIdx.x == 0) ? 0 : sp[blockIdx.x - 1];
    if (blockIdx.x == 0 && t == 0) g_off[N_NODES] = sp[NPART - 1];

    const int i = blockIdx.x * 256 + t;
    const int v = (i < N_NODES) ? g_cnt[i] : 0;
    s[t] = v;
    __syncthreads();
#pragma unroll
    for (int off = 1; off < 256; off <<= 1) {
        int u = (t >= off) ? s[t - off] : 0;
        __syncthreads();
        s[t] += u;
        __syncthreads();
    }
    if (i < N_NODES) {
        g_off[i] = s[t] - v + blk_prefix;
        g_dis[i] = (v > 0) ? rsqrtf((float)v) : 0.f;
    }
}

__global__ void k_fill_csr() {
    int e = blockIdx.x * blockDim.x + threadIdx.x;
    if (e >= N_EDGES) return;
    unsigned r = (unsigned)g_row[e];
    unsigned c = (unsigned)g_col[e];
    if (r >= N_NODES || c >= N_NODES) return;
    int pos = g_off[r] + atomicAdd(&g_cur[r], 1);
    g_ecol[pos] = (int)c;
}

// ---------------------------------------------------------------------------
// y = x @ W^T via mma.sync m16n8k8 3xTF32. Fully unrolled kc loop (MLP),
// B frags pre-packed in g_Wf (L1-resident); ONE __syncthreads total.
__global__ void __launch_bounds__(256, 2) k_gemm_mma(const float* __restrict__ x) {
    __shared__ float xs[GM][132];   // pad 132: A-frag LDS conflict-free

    const int tid = threadIdx.x;
    const int wid = tid >> 5, lane = tid & 31;
    const int g = lane >> 2, t = lane & 3;
    const int mg = wid >> 2;        // 0..1  -> rows mg*32 + mt*16
    const int ng = wid & 3;         // 0..3  -> nt = ng*4 + ntl
    const int row0 = blockIdx.x * GM;

    // Load x tile (coalesced float4; zero-pad tail rows)
    for (int i = tid; i < GM * 32; i += 256) {
        int r = i >> 5, q = i & 31;
        float4 v = make_float4(0.f, 0.f, 0.f, 0.f);
        if (row0 + r < N_NODES)
            v = ((const float4*)(x + (size_t)(row0 + r) * C))[q];
        *(float4*)&xs[r][4 * q] = v;
    }
    __syncthreads();

    float4 acc[2][4];
#pragma unroll
    for (int mt = 0; mt < 2; mt++)
#pragma unroll
        for (int n = 0; n < 4; n++) acc[mt][n] = make_float4(0.f, 0.f, 0.f, 0.f);

    const float4* wf = g_Wf + (size_t)(ng * 4) * 32 + lane;

#pragma unroll
    for (int kc = 0; kc < 16; kc++) {
        const int k0 = kc * 8;
        // B fragments first (independent LDG.128s -> front-batched by ptxas)
        float4 bf[4];
#pragma unroll
        for (int ntl = 0; ntl < 4; ntl++)
            bf[ntl] = __ldg(wf + (size_t)(kc * 16 + ntl) * 32);

        // A fragments for 2 m-tiles (hi/lo split on the fly)
        uint32_t ah[2][4], al[2][4];
#pragma unroll
        for (int mt = 0; mt < 2; mt++) {
            const int r0 = mg * 32 + mt * 16 + g;
            float v0 = xs[r0][k0 + t];
            float v1 = xs[r0 + 8][k0 + t];
            float v2 = xs[r0][k0 + t + 4];
            float v3 = xs[r0 + 8][k0 + t + 4];
            ah[mt][0] = tf32r(v0); al[mt][0] = tf32r(v0 - __uint_as_float(ah[mt][0]));
            ah[mt][1] = tf32r(v1); al[mt][1] = tf32r(v1 - __uint_as_float(ah[mt][1]));
            ah[mt][2] = tf32r(v2); al[mt][2] = tf32r(v2 - __uint_as_float(ah[mt][2]));
            ah[mt][3] = tf32r(v3); al[mt][3] = tf32r(v3 - __uint_as_float(ah[mt][3]));
        }
#pragma unroll
        for (int ntl = 0; ntl < 4; ntl++) {
            const uint32_t h0 = __float_as_uint(bf[ntl].x), h1 = __float_as_uint(bf[ntl].y);
            const uint32_t l0 = __float_as_uint(bf[ntl].z), l1 = __float_as_uint(bf[ntl].w);
#pragma unroll
            for (int mt = 0; mt < 2; mt++) {
                mma8(acc[mt][ntl], ah[mt], h0, h1);   // hi*hi
                mma8(acc[mt][ntl], ah[mt], l0, l1);   // hi*lo
                mma8(acc[mt][ntl], al[mt], h0, h1);   // lo*hi
            }
        }
    }

    // Epilogue: c0/c1 -> (row g, cols 2t,2t+1), c2/c3 -> row g+8
#pragma unroll
    for (int mt = 0; mt < 2; mt++) {
        const size_t gr0 = (size_t)(row0 + mg * 32 + mt * 16 + g) * C;
        const size_t gr1 = gr0 + 8 * C;
#pragma unroll
        for (int ntl = 0; ntl < 4; ntl++) {
            const int cb = (ng * 4 + ntl) * 8 + 2 * t;
            *(float2*)&g_y[gr0 + cb] = make_float2(acc[mt][ntl].x, acc[mt][ntl].y);
            *(float2*)&g_y[gr1 + cb] = make_float2(acc[mt][ntl].z, acc[mt][ntl].w);
        }
    }
}

// ---------------------------------------------------------------------------
// Warp per node: out[n] = b + dis[n] * sum_e dis[col_e] * y[col_e]
__global__ void __launch_bounds__(256) k_gather(float* __restrict__ out,
                                                const float* __restrict__ b) {
    int gtid = blockIdx.x * blockDim.x + threadIdx.x;
    int n = gtid >> 5;
    int lane = gtid & 31;
    if (n >= N_NODES) return;

    const float4 bias = __ldg(((const float4*)b) + lane);
    float ax = 0.f, ay = 0.f, az = 0.f, aw = 0.f;

    const int start = g_off[n];
    const int end = g_off[n + 1];
    const float dn = g_dis[n];

    for (int e = start; e < end; e++) {
        int c = g_ecol[e];
        float norm = dn * g_dis[c];
        float4 v = __ldg(((const float4*)(g_y + (size_t)c * C)) + lane);
        ax += norm * v.x;
        ay += norm * v.y;
        az += norm * v.z;
        aw += norm * v.w;
    }

    ((float4*)(out + (size_t)n * C))[lane] =
        make_float4(bias.x + ax, bias.y + ay, bias.z + az, bias.w + aw);
}

// ---------------------------------------------------------------------------
extern "C" void kernel_launch(void* const* d_in, const int* in_sizes, int n_in,
                              void* d_out, int out_size) {
    const float* x = (const float*)d_in[0];
    const void*  ei = d_in[1];
    const float* W = (const float*)d_in[2];
    const float* b = (const float*)d_in[3];
    float* out = (float*)d_out;

    // Fork/join: CSR chain runs on a side stream, overlapped with the GEMM.
    cudaStream_t s2;
    cudaStreamCreateWithFlags(&s2, cudaStreamNonBlocking);
    cudaEvent_t evFork, evJoin;
    cudaEventCreateWithFlags(&evFork, cudaEventDisableTiming);
    cudaEventCreateWithFlags(&evJoin, cudaEventDisableTiming);

    k_detect_prep<<<(N_NODES + 255) / 256, 256>>>((const long long*)ei, W);   // 1
    cudaEventRecord(evFork, 0);
    cudaStreamWaitEvent(s2, evFork, 0);

    k_edges<<<(N_EDGES + 255) / 256, 256, 0, s2>>>(ei);                       // 2
    k_scan1<<<NPART, 256, 0, s2>>>();                                         // 3
    k_gemm_mma<<<GBLKS, 256>>>(x);                                            // 4 (profiled)
    k_scan_off<<<NPART, 256, 0, s2>>>();                                      // 5
    k_fill_csr<<<(N_EDGES + 255) / 256, 256, 0, s2>>>();                      // 6
    cudaEventRecord(evJoin, s2);
    cudaStreamWaitEvent(0, evJoin, 0);

    const long long total = (long long)N_NODES * 32;
    k_gather<<<(int)((total + 255) / 256), 256>>>(out, b);                    // 7

    cudaEventDestroy(evFork);
    cudaEventDestroy(evJoin);
    cudaStreamDestroy(s2);
}

// round 12
// speedup vs baseline: 1.5486x; 1.0082x over previous
#include <cuda_runtime.h>
#include <cuda_bf16.h>
#include <cstdint>

#define N_NODES 50000
#define N_EDGES 625000
#define C 128
#define NPART ((N_NODES + 255) / 256)   // 196 scan blocks
#define GM 64                            // GEMM rows per block
#define GBLKS ((N_NODES + GM - 1) / GM)  // 782
#define PADROWS (GBLKS * GM)             // 50048
#define NFRAG (16 * 16 * 32)             // kc * nt * lane = 8192

// Scratch (__device__ globals; allocations are banned)
__device__ __align__(16) float  g_y[(size_t)PADROWS * C];  // x @ W^T (row-padded)
__device__ __align__(16) float4 g_Wf[NFRAG];  // pre-packed B frags (hi0,hi1,lo0,lo1)
__device__ float g_dis[N_NODES];             // deg^-1/2
__device__ int   g_row[N_EDGES];
__device__ int   g_col[N_EDGES];
__device__ int   g_cnt[N_NODES];             // degree counts
__device__ int   g_cur[N_NODES];             // fill cursors
__device__ int   g_off[N_NODES + 1];         // CSR offsets
__device__ int   g_ecol[N_EDGES];            // CSR column (src) ids
__device__ int   g_part[NPART];              // scan partials
__device__ int   g_is64;

// ---------------------------------------------------------------------------
static __device__ __forceinline__ uint32_t tf32r(float v) {
    uint32_t r;
    asm("cvt.rna.tf32.f32 %0, %1;" : "=r"(r) : "f"(v));
    return r;
}

static __device__ __forceinline__ void mma8(float4& d, const uint32_t* a,
                                            uint32_t b0, uint32_t b1) {
    asm volatile(
        "mma.sync.aligned.m16n8k8.row.col.f32.tf32.tf32.f32 "
        "{%0,%1,%2,%3}, {%4,%5,%6,%7}, {%8,%9}, {%0,%1,%2,%3};"
        : "+f"(d.x), "+f"(d.y), "+f"(d.z), "+f"(d.w)
        : "r"(a[0]), "r"(a[1]), "r"(a[2]), "r"(a[3]), "r"(b0), "r"(b1));
}

// ---------------------------------------------------------------------------
// Fused: dtype detect (block 0) + zero counters + B-fragment pack of W.
__global__ void k_detect_prep(const long long* __restrict__ ei,
                              const float* __restrict__ W) {
    int i = blockIdx.x * blockDim.x + threadIdx.x;
    if (i < N_NODES) { g_cnt[i] = 0; g_cur[i] = 0; }
    if (i < NFRAG) {
        int lane = i & 31;
        int frag = i >> 5;
        int nt = frag & 15;
        int kc = frag >> 4;
        int n = nt * 8 + (lane >> 2);
        int k = kc * 8 + (lane & 3);
        float w0 = W[n * C + k];
        float w1 = W[n * C + k + 4];
        float h0 = __uint_as_float(tf32r(w0));
        float h1 = __uint_as_float(tf32r(w1));
        float l0 = __uint_as_float(tf32r(w0 - h0));
        float l1 = __uint_as_float(tf32r(w1 - h1));
        g_Wf[i] = make_float4(h0, h1, l0, l1);
    }
    if (blockIdx.x == 0) {
        __shared__ int ok;
        if (threadIdx.x == 0) ok = 1;
        __syncthreads();
        for (int s = threadIdx.x; s < 1024; s += blockDim.x) {
            long long v = ei[s];
            if (v < 0 || v >= N_NODES) atomicExch(&ok, 0);
        }
        __syncthreads();
        if (threadIdx.x == 0) g_is64 = ok;
    }
}

// normalize edges + count degrees in one pass
__global__ void k_edges(const void* __restrict__ ei) {
    int e = blockIdx.x * blockDim.x + threadIdx.x;
    if (e >= N_EDGES) return;
    int r, c;
    if (g_is64) {
        const long long* p = (const long long*)ei;
        r = (int)p[e];
        c = (int)p[e + N_EDGES];
    } else {
        const int* p = (const int*)ei;
        r = p[e];
        c = p[e + N_EDGES];
    }
    g_row[e] = r;
    g_col[e] = c;
    if ((unsigned)r < N_NODES) atomicAdd(&g_cnt[r], 1);
}

// ---------------------------------------------------------------------------
__global__ void __launch_bounds__(256) k_scan1() {
    __shared__ int s[256];
    const int t = threadIdx.x;
    const int i = blockIdx.x * 256 + t;
    s[t] = (i < N_NODES) ? g_cnt[i] : 0;
    __syncthreads();
#pragma unroll
    for (int off = 128; off > 0; off >>= 1) {
        if (t < off) s[t] += s[t + off];
        __syncthreads();
    }
    if (t == 0) g_part[blockIdx.x] = s[0];
}

__global__ void __launch_bounds__(256) k_scan_off() {
    __shared__ int sp[256];
    __shared__ int s[256];
    const int t = threadIdx.x;

    const int pv = (t < NPART) ? g_part[t] : 0;
    sp[t] = pv;
    __syncthreads();
#pragma unroll
    for (int off = 1; off < 256; off <<= 1) {
        int u = (t >= off) ? sp[t - off] : 0;
        __syncthreads();
        sp[t] += u;
        __syncthreads();
    }
    const int blk_prefix = (blockIdx.x == 0) ? 0 : sp[blockIdx.x - 1];
    if (blockIdx.x == 0 && t == 0) g_off[N_NODES] = sp[NPART - 1];

    const int i = blockIdx.x * 256 + t;
    const int v = (i < N_NODES) ? g_cnt[i] : 0;
    s[t] = v;
    __syncthreads();
#pragma unroll
    for (int off = 1; off < 256; off <<= 1) {
        int u = (t >= off) ? s[t - off] : 0;
        __syncthreads();
        s[t] += u;
        __syncthreads();
    }
    if (i < N_NODES) {
        g_off[i] = s[t] - v + blk_prefix;
        g_dis[i] = (v > 0) ? rsqrtf((float)v) : 0.f;
    }
}

__global__ void k_fill_csr() {
    int e = blockIdx.x * blockDim.x + threadIdx.x;
    if (e >= N_EDGES) return;
    unsigned r = (unsigned)g_row[e];
    unsigned c = (unsigned)g_col[e];
    if (r >= N_NODES || c >= N_NODES) return;
    int pos = g_off[r] + atomicAdd(&g_cur[r], 1);
    g_ecol[pos] = (int)c;
}

// ---------------------------------------------------------------------------
// y = x @ W^T via mma.sync m16n8k8 3xTF32. occupancy-targeted (3 CTAs/SM),
// B frags pre-packed in g_Wf (L1-resident); ONE __syncthreads total.
__global__ void __launch_bounds__(256, 3) k_gemm_mma(const float* __restrict__ x) {
    __shared__ float xs[GM][132];   // pad 132: A-frag LDS conflict-free

    const int tid = threadIdx.x;
    const int wid = tid >> 5, lane = tid & 31;
    const int g = lane >> 2, t = lane & 3;
    const int mg = wid >> 2;        // 0..1  -> rows mg*32 + mt*16
    const int ng = wid & 3;         // 0..3  -> nt = ng*4 + ntl
    const int row0 = blockIdx.x * GM;

    // Load x tile (coalesced float4; zero-pad tail rows)
    for (int i = tid; i < GM * 32; i += 256) {
        int r = i >> 5, q = i & 31;
        float4 v = make_float4(0.f, 0.f, 0.f, 0.f);
        if (row0 + r < N_NODES)
            v = ((const float4*)(x + (size_t)(row0 + r) * C))[q];
        *(float4*)&xs[r][4 * q] = v;
    }
    __syncthreads();

    float4 acc[2][4];
#pragma unroll
    for (int mt = 0; mt < 2; mt++)
#pragma unroll
        for (int n = 0; n < 4; n++) acc[mt][n] = make_float4(0.f, 0.f, 0.f, 0.f);

    const float4* wf = g_Wf + (size_t)(ng * 4) * 32 + lane;

#pragma unroll 8
    for (int kc = 0; kc < 16; kc++) {
        const int k0 = kc * 8;
        // B fragments first (independent LDG.128s -> front-batched)
        float4 bf[4];
#pragma unroll
        for (int ntl = 0; ntl < 4; ntl++)
            bf[ntl] = __ldg(wf + (size_t)(kc * 16 + ntl) * 32);

        // A fragments for 2 m-tiles (hi/lo split on the fly)
        uint32_t ah[2][4], al[2][4];
#pragma unroll
        for (int mt = 0; mt < 2; mt++) {
            const int r0 = mg * 32 + mt * 16 + g;
            float v0 = xs[r0][k0 + t];
            float v1 = xs[r0 + 8][k0 + t];
            float v2 = xs[r0][k0 + t + 4];
            float v3 = xs[r0 + 8][k0 + t + 4];
            ah[mt][0] = tf32r(v0); al[mt][0] = tf32r(v0 - __uint_as_float(ah[mt][0]));
            ah[mt][1] = tf32r(v1); al[mt][1] = tf32r(v1 - __uint_as_float(ah[mt][1]));
            ah[mt][2] = tf32r(v2); al[mt][2] = tf32r(v2 - __uint_as_float(ah[mt][2]));
            ah[mt][3] = tf32r(v3); al[mt][3] = tf32r(v3 - __uint_as_float(ah[mt][3]));
        }
#pragma unroll
        for (int ntl = 0; ntl < 4; ntl++) {
            const uint32_t h0 = __float_as_uint(bf[ntl].x), h1 = __float_as_uint(bf[ntl].y);
            const uint32_t l0 = __float_as_uint(bf[ntl].z), l1 = __float_as_uint(bf[ntl].w);
#pragma unroll
            for (int mt = 0; mt < 2; mt++) {
                mma8(acc[mt][ntl], ah[mt], h0, h1);   // hi*hi
                mma8(acc[mt][ntl], ah[mt], l0, l1);   // hi*lo
                mma8(acc[mt][ntl], al[mt], h0, h1);   // lo*hi
            }
        }
    }

    // Epilogue: c0/c1 -> (row g, cols 2t,2t+1), c2/c3 -> row g+8
#pragma unroll
    for (int mt = 0; mt < 2; mt++) {
        const size_t gr0 = (size_t)(row0 + mg * 32 + mt * 16 + g) * C;
        const size_t gr1 = gr0 + 8 * C;
#pragma unroll
        for (int ntl = 0; ntl < 4; ntl++) {
            const int cb = (ng * 4 + ntl) * 8 + 2 * t;
            *(float2*)&g_y[gr0 + cb] = make_float2(acc[mt][ntl].x, acc[mt][ntl].y);
            *(float2*)&g_y[gr1 + cb] = make_float2(acc[mt][ntl].z, acc[mt][ntl].w);
        }
    }
}

// ---------------------------------------------------------------------------
// Warp per node, 2-edge unrolled for MLP:
// out[n] = b + dis[n] * sum_e dis[col_e] * y[col_e]
__global__ void __launch_bounds__(256) k_gather(float* __restrict__ out,
                                                const float* __restrict__ b) {
    int gtid = blockIdx.x * blockDim.x + threadIdx.x;
    int n = gtid >> 5;
    int lane = gtid & 31;
    if (n >= N_NODES) return;

    const float4 bias = __ldg(((const float4*)b) + lane);
    float ax = 0.f, ay = 0.f, az = 0.f, aw = 0.f;

    const int start = g_off[n];
    const int end = g_off[n + 1];
    const float dn = g_dis[n];

    int e = start;
    for (; e + 2 <= end; e += 2) {
        int c0 = g_ecol[e];
        int c1 = g_ecol[e + 1];
        float m0 = dn * g_dis[c0];
        float m1 = dn * g_dis[c1];
        float4 v0 = __ldg(((const float4*)(g_y + (size_t)c0 * C)) + lane);
        float4 v1 = __ldg(((const float4*)(g_y + (size_t)c1 * C)) + lane);
        ax += m0 * v0.x + m1 * v1.x;
        ay += m0 * v0.y + m1 * v1.y;
        az += m0 * v0.z + m1 * v1.z;
        aw += m0 * v0.w + m1 * v1.w;
    }
    if (e < end) {
        int c = g_ecol[e];
        float m = dn * g_dis[c];
        float4 v = __ldg(((const float4*)(g_y + (size_t)c * C)) + lane);
        ax += m * v.x;
        ay += m * v.y;
        az += m * v.z;
        aw += m * v.w;
    }

    ((float4*)(out + (size_t)n * C))[lane] =
        make_float4(bias.x + ax, bias.y + ay, bias.z + az, bias.w + aw);
}

// ---------------------------------------------------------------------------
extern "C" void kernel_launch(void* const* d_in, const int* in_sizes, int n_in,
                              void* d_out, int out_size) {
    const float* x = (const float*)d_in[0];
    const void*  ei = d_in[1];
    const float* W = (const float*)d_in[2];
    const float* b = (const float*)d_in[3];
    float* out = (float*)d_out;

    // Fork/join: CSR chain runs on a side stream, overlapped with the GEMM.
    cudaStream_t s2;
    cudaStreamCreateWithFlags(&s2, cudaStreamNonBlocking);
    cudaEvent_t evFork, evJoin;
    cudaEventCreateWithFlags(&evFork, cudaEventDisableTiming);
    cudaEventCreateWithFlags(&evJoin, cudaEventDisableTiming);

    k_detect_prep<<<(N_NODES + 255) / 256, 256>>>((const long long*)ei, W);   // 1
    cudaEventRecord(evFork, 0);
    cudaStreamWaitEvent(s2, evFork, 0);

    k_edges<<<(N_EDGES + 255) / 256, 256, 0, s2>>>(ei);                       // 2
    k_scan1<<<NPART, 256, 0, s2>>>();                                         // 3
    k_gemm_mma<<<GBLKS, 256>>>(x);                                            // 4 (profiled)
    k_scan_off<<<NPART, 256, 0, s2>>>();                                      // 5
    k_fill_csr<<<(N_EDGES + 255) / 256, 256, 0, s2>>>();                      // 6
    cudaEventRecord(evJoin, s2);
    cudaStreamWaitEvent(0, evJoin, 0);

    const long long total = (long long)N_NODES * 32;
    k_gather<<<(int)((total + 255) / 256), 256>>>(out, b);                    // 7

    cudaEventDestroy(evFork);
    cudaEventDestroy(evJoin);
    cudaStreamDestroy(s2);
}

// round 13
// speedup vs baseline: 1.6745x; 1.0813x over previous
#include <cuda_runtime.h>
#include <cuda_fp16.h>
#include <cuda_bf16.h>
#include <cstdint>

#define N_NODES 50000
#define N_EDGES 625000
#define C 128
#define NPART ((N_NODES + 255) / 256)   // 196 scan blocks
#define GM 64                            // GEMM rows per block
#define GBLKS ((N_NODES + GM - 1) / GM)  // 782
#define PADROWS (GBLKS * GM)             // 50048
#define NFRAG (16 * 16 * 32)             // kc * nt * lane = 8192

// Scratch (__device__ globals; allocations are banned)
__device__ __align__(16) __half g_yh[(size_t)PADROWS * C];  // x @ W^T, fp16
__device__ __align__(16) float4 g_Wf[NFRAG];  // pre-packed B frags (hi0,hi1,lo0,lo1)
__device__ float g_dis[N_NODES];             // deg^-1/2
__device__ int   g_row[N_EDGES];
__device__ int   g_col[N_EDGES];
__device__ int   g_cnt[N_NODES];             // degree counts
__device__ int   g_cur[N_NODES];             // fill cursors
__device__ int   g_off[N_NODES + 1];         // CSR offsets
__device__ int   g_ecol[N_EDGES];            // CSR column (src) ids
__device__ int   g_part[NPART];              // scan partials
__device__ int   g_is64;

// ---------------------------------------------------------------------------
static __device__ __forceinline__ uint32_t tf32r(float v) {
    uint32_t r;
    asm("cvt.rna.tf32.f32 %0, %1;" : "=r"(r) : "f"(v));
    return r;
}

static __device__ __forceinline__ void mma8(float4& d, const uint32_t* a,
                                            uint32_t b0, uint32_t b1) {
    asm volatile(
        "mma.sync.aligned.m16n8k8.row.col.f32.tf32.tf32.f32 "
        "{%0,%1,%2,%3}, {%4,%5,%6,%7}, {%8,%9}, {%0,%1,%2,%3};"
        : "+f"(d.x), "+f"(d.y), "+f"(d.z), "+f"(d.w)
        : "r"(a[0]), "r"(a[1]), "r"(a[2]), "r"(a[3]), "r"(b0), "r"(b1));
}

// ---------------------------------------------------------------------------
// Fused: dtype detect (block 0) + zero counters + B-fragment pack of W.
__global__ void k_detect_prep(const long long* __restrict__ ei,
                              const float* __restrict__ W) {
    int i = blockIdx.x * blockDim.x + threadIdx.x;
    if (i < N_NODES) { g_cnt[i] = 0; g_cur[i] = 0; }
    if (i < NFRAG) {
        int lane = i & 31;
        int frag = i >> 5;
        int nt = frag & 15;
        int kc = frag >> 4;
        int n = nt * 8 + (lane >> 2);
        int k = kc * 8 + (lane & 3);
        float w0 = W[n * C + k];
        float w1 = W[n * C + k + 4];
        float h0 = __uint_as_float(tf32r(w0));
        float h1 = __uint_as_float(tf32r(w1));
        float l0 = __uint_as_float(tf32r(w0 - h0));
        float l1 = __uint_as_float(tf32r(w1 - h1));
        g_Wf[i] = make_float4(h0, h1, l0, l1);
    }
    if (blockIdx.x == 0) {
        __shared__ int ok;
        if (threadIdx.x == 0) ok = 1;
        __syncthreads();
        for (int s = threadIdx.x; s < 1024; s += blockDim.x) {
            long long v = ei[s];
            if (v < 0 || v >= N_NODES) atomicExch(&ok, 0);
        }
        __syncthreads();
        if (threadIdx.x == 0) g_is64 = ok;
    }
}

// normalize edges + count degrees in one pass
__global__ void k_edges(const void* __restrict__ ei) {
    int e = blockIdx.x * blockDim.x + threadIdx.x;
    if (e >= N_EDGES) return;
    int r, c;
    if (g_is64) {
        const long long* p = (const long long*)ei;
        r = (int)p[e];
        c = (int)p[e + N_EDGES];
    } else {
        const int* p = (const int*)ei;
        r = p[e];
        c = p[e + N_EDGES];
    }
    g_row[e] = r;
    g_col[e] = c;
    if ((unsigned)r < N_NODES) atomicAdd(&g_cnt[r], 1);
}

// ---------------------------------------------------------------------------
__global__ void __launch_bounds__(256) k_scan1() {
    __shared__ int s[256];
    const int t = threadIdx.x;
    const int i = blockIdx.x * 256 + t;
    s[t] = (i < N_NODES) ? g_cnt[i] : 0;
    __syncthreads();
#pragma unroll
    for (int off = 128; off > 0; off >>= 1) {
        if (t < off) s[t] += s[t + off];
        __syncthreads();
    }
    if (t == 0) g_part[blockIdx.x] = s[0];
}

__global__ void __launch_bounds__(256) k_scan_off() {
    __shared__ int sp[256];
    __shared__ int s[256];
    const int t = threadIdx.x;

    const int pv = (t < NPART) ? g_part[t] : 0;
    sp[t] = pv;
    __syncthreads();
#pragma unroll
    for (int off = 1; off < 256; off <<= 1) {
        int u = (t >= off) ? sp[t - off] : 0;
        __syncthreads();
        sp[t] += u;
        __syncthreads();
    }
    const int blk_prefix = (blockIdx.x == 0) ? 0 : sp[blockIdx.x - 1];
    if (blockIdx.x == 0 && t == 0) g_off[N_NODES] = sp[NPART - 1];

    const int i = blockIdx.x * 256 + t;
    const int v = (i < N_NODES) ? g_cnt[i] : 0;
    s[t] = v;
    __syncthreads();
#pragma unroll
    for (int off = 1; off < 256; off <<= 1) {
        int u = (t >= off) ? s[t - off] : 0;
        __syncthreads();
        s[t] += u;
        __syncthreads();
    }
    if (i < N_NODES) {
        g_off[i] = s[t] - v + blk_prefix;
        g_dis[i] = (v > 0) ? rsqrtf((float)v) : 0.f;
    }
}

__global__ void k_fill_csr() {
    int e = blockIdx.x * blockDim.x + threadIdx.x;
    if (e >= N_EDGES) return;
    unsigned r = (unsigned)g_row[e];
    unsigned c = (unsigned)g_col[e];
    if (r >= N_NODES || c >= N_NODES) return;
    int pos = g_off[r] + atomicAdd(&g_cur[r], 1);
    g_ecol[pos] = (int)c;
}

// ---------------------------------------------------------------------------
// y = x @ W^T via mma.sync m16n8k8 3xTF32. R11-proven config: (256,2),
// fully unrolled kc loop; fp32 accum, fp16 store.
__global__ void __launch_bounds__(256, 2) k_gemm_mma(const float* __restrict__ x) {
    __shared__ float xs[GM][132];   // pad 132: A-frag LDS conflict-free

    const int tid = threadIdx.x;
    const int wid = tid >> 5, lane = tid & 31;
    const int g = lane >> 2, t = lane & 3;
    const int mg = wid >> 2;        // 0..1  -> rows mg*32 + mt*16
    const int ng = wid & 3;         // 0..3  -> nt = ng*4 + ntl
    const int row0 = blockIdx.x * GM;

    // Load x tile (coalesced float4; zero-pad tail rows)
    for (int i = tid; i < GM * 32; i += 256) {
        int r = i >> 5, q = i & 31;
        float4 v = make_float4(0.f, 0.f, 0.f, 0.f);
        if (row0 + r < N_NODES)
            v = ((const float4*)(x + (size_t)(row0 + r) * C))[q];
        *(float4*)&xs[r][4 * q] = v;
    }
    __syncthreads();

    float4 acc[2][4];
#pragma unroll
    for (int mt = 0; mt < 2; mt++)
#pragma unroll
        for (int n = 0; n < 4; n++) acc[mt][n] = make_float4(0.f, 0.f, 0.f, 0.f);

    const float4* wf = g_Wf + (size_t)(ng * 4) * 32 + lane;

#pragma unroll
    for (int kc = 0; kc < 16; kc++) {
        const int k0 = kc * 8;
        // B fragments first (independent LDG.128s -> front-batched)
        float4 bf[4];
#pragma unroll
        for (int ntl = 0; ntl < 4; ntl++)
            bf[ntl] = __ldg(wf + (size_t)(kc * 16 + ntl) * 32);

        // A fragments for 2 m-tiles (hi/lo split on the fly)
        uint32_t ah[2][4], al[2][4];
#pragma unroll
        for (int mt = 0; mt < 2; mt++) {
            const int r0 = mg * 32 + mt * 16 + g;
            float v0 = xs[r0][k0 + t];
            float v1 = xs[r0 + 8][k0 + t];
            float v2 = xs[r0][k0 + t + 4];
            float v3 = xs[r0 + 8][k0 + t + 4];
            ah[mt][0] = tf32r(v0); al[mt][0] = tf32r(v0 - __uint_as_float(ah[mt][0]));
            ah[mt][1] = tf32r(v1); al[mt][1] = tf32r(v1 - __uint_as_float(ah[mt][1]));
            ah[mt][2] = tf32r(v2); al[mt][2] = tf32r(v2 - __uint_as_float(ah[mt][2]));
            ah[mt][3] = tf32r(v3); al[mt][3] = tf32r(v3 - __uint_as_float(ah[mt][3]));
        }
#pragma unroll
        for (int ntl = 0; ntl < 4; ntl++) {
            const uint32_t h0 = __float_as_uint(bf[ntl].x), h1 = __float_as_uint(bf[ntl].y);
            const uint32_t l0 = __float_as_uint(bf[ntl].z), l1 = __float_as_uint(bf[ntl].w);
#pragma unroll
            for (int mt = 0; mt < 2; mt++) {
                mma8(acc[mt][ntl], ah[mt], h0, h1);   // hi*hi
                mma8(acc[mt][ntl], ah[mt], l0, l1);   // hi*lo
                mma8(acc[mt][ntl], al[mt], h0, h1);   // lo*hi
            }
        }
    }

    // Epilogue: fp32 acc -> fp16; c0/c1 -> (row g, cols 2t,2t+1), c2/c3 -> row g+8
#pragma unroll
    for (int mt = 0; mt < 2; mt++) {
        const size_t gr0 = (size_t)(row0 + mg * 32 + mt * 16 + g) * C;
        const size_t gr1 = gr0 + 8 * C;
#pragma unroll
        for (int ntl = 0; ntl < 4; ntl++) {
            const int cb = (ng * 4 + ntl) * 8 + 2 * t;
            *(__half2*)&g_yh[gr0 + cb] = __floats2half2_rn(acc[mt][ntl].x, acc[mt][ntl].y);
            *(__half2*)&g_yh[gr1 + cb] = __floats2half2_rn(acc[mt][ntl].z, acc[mt][ntl].w);
        }
    }
}

// ---------------------------------------------------------------------------
// Warp per node, 2-edge unrolled; y rows read as fp16 (half L2 traffic):
// out[n] = b + dis[n] * sum_e dis[col_e] * y[col_e]
__global__ void __launch_bounds__(256) k_gather(float* __restrict__ out,
                                                const float* __restrict__ b) {
    int gtid = blockIdx.x * blockDim.x + threadIdx.x;
    int n = gtid >> 5;
    int lane = gtid & 31;
    if (n >= N_NODES) return;

    const float4 bias = __ldg(((const float4*)b) + lane);
    float ax = 0.f, ay = 0.f, az = 0.f, aw = 0.f;

    const int start = g_off[n];
    const int end = g_off[n + 1];
    const float dn = g_dis[n];

    int e = start;
    for (; e + 2 <= end; e += 2) {
        int c0 = g_ecol[e];
        int c1 = g_ecol[e + 1];
        float m0 = dn * g_dis[c0];
        float m1 = dn * g_dis[c1];
        uint2 u0 = __ldg(((const uint2*)(g_yh + (size_t)c0 * C)) + lane);
        uint2 u1 = __ldg(((const uint2*)(g_yh + (size_t)c1 * C)) + lane);
        float2 a0 = __half22float2(*(__half2*)&u0.x);
        float2 b0v = __half22float2(*(__half2*)&u0.y);
        float2 a1 = __half22float2(*(__half2*)&u1.x);
        float2 b1v = __half22float2(*(__half2*)&u1.y);
        ax += m0 * a0.x + m1 * a1.x;
        ay += m0 * a0.y + m1 * a1.y;
        az += m0 * b0v.x + m1 * b1v.x;
        aw += m0 * b0v.y + m1 * b1v.y;
    }
    if (e < end) {
        int c = g_ecol[e];
        float m = dn * g_dis[c];
        uint2 u = __ldg(((const uint2*)(g_yh + (size_t)c * C)) + lane);
        float2 a0 = __half22float2(*(__half2*)&u.x);
        float2 b0v = __half22float2(*(__half2*)&u.y);
        ax += m * a0.x;
        ay += m * a0.y;
        az += m * b0v.x;
        aw += m * b0v.y;
    }

    ((float4*)(out + (size_t)n * C))[lane] =
        make_float4(bias.x + ax, bias.y + ay, bias.z + az, bias.w + aw);
}

// ---------------------------------------------------------------------------
extern "C" void kernel_launch(void* const* d_in, const int* in_sizes, int n_in,
                              void* d_out, int out_size) {
    const float* x = (const float*)d_in[0];
    const void*  ei = d_in[1];
    const float* W = (const float*)d_in[2];
    const float* b = (const float*)d_in[3];
    float* out = (float*)d_out;

    // Fork/join: CSR chain runs on a side stream, overlapped with the GEMM.
    cudaStream_t s2;
    cudaStreamCreateWithFlags(&s2, cudaStreamNonBlocking);
    cudaEvent_t evFork, evJoin;
    cudaEventCreateWithFlags(&evFork, cudaEventDisableTiming);
    cudaEventCreateWithFlags(&evJoin, cudaEventDisableTiming);

    k_detect_prep<<<(N_NODES + 255) / 256, 256>>>((const long long*)ei, W);   // 1
    cudaEventRecord(evFork, 0);
    cudaStreamWaitEvent(s2, evFork, 0);

    k_edges<<<(N_EDGES + 255) / 256, 256, 0, s2>>>(ei);                       // 2
    k_scan1<<<NPART, 256, 0, s2>>>();                                         // 3
    k_gemm_mma<<<GBLKS, 256>>>(x);                                            // 4 (profiled)
    k_scan_off<<<NPART, 256, 0, s2>>>();                                      // 5
    k_fill_csr<<<(N_EDGES + 255) / 256, 256, 0, s2>>>();                      // 6
    cudaEventRecord(evJoin, s2);
    cudaStreamWaitEvent(0, evJoin, 0);

    const long long total = (long long)N_NODES * 32;
    k_gather<<<(int)((total + 255) / 256), 256>>>(out, b);                    // 7

    cudaEventDestroy(evFork);
    cudaEventDestroy(evJoin);
    cudaStreamDestroy(s2);
}

// round 14
// speedup vs baseline: 1.8341x; 1.0953x over previous
#include <cuda_runtime.h>
#include <cuda_fp16.h>
#include <cuda_bf16.h>
#include <cstdint>

#define N_NODES 50000
#define N_EDGES 625000
#define C 128
#define NPART ((N_NODES + 255) / 256)   // 196 scan blocks
#define GM 64                            // GEMM rows per block
#define GBLKS ((N_NODES + GM - 1) / GM)  // 782
#define PADROWS (GBLKS * GM)             // 50048
#define NFRAG (8 * 16 * 32)              // kc16 * nt * lane = 4096

// Scratch (__device__ globals; allocations are banned)
__device__ __align__(16) __half g_yh[(size_t)PADROWS * C];  // x @ W^T, fp16
__device__ __align__(16) uint4  g_Wf[NFRAG];  // B frags: (hi0,hi1,lo0,lo1) bf16x2
__device__ float g_dis[N_NODES];             // deg^-1/2
__device__ int   g_row[N_EDGES];
__device__ int   g_col[N_EDGES];
__device__ int   g_cnt[N_NODES];             // degree counts
__device__ int   g_cur[N_NODES];             // fill cursors
__device__ int   g_off[N_NODES + 1];         // CSR offsets
__device__ int   g_ecol[N_EDGES];            // CSR column (src) ids
__device__ int   g_part[NPART];              // scan partials
__device__ int   g_is64;

// ---------------------------------------------------------------------------
static __device__ __forceinline__ void mma16(float4& d, const uint32_t* a,
                                             uint32_t b0, uint32_t b1) {
    asm volatile(
        "mma.sync.aligned.m16n8k16.row.col.f32.bf16.bf16.f32 "
        "{%0,%1,%2,%3}, {%4,%5,%6,%7}, {%8,%9}, {%0,%1,%2,%3};"
        : "+f"(d.x), "+f"(d.y), "+f"(d.z), "+f"(d.w)
        : "r"(a[0]), "r"(a[1]), "r"(a[2]), "r"(a[3]), "r"(b0), "r"(b1));
}

// Split a float pair into bf16x2 hi and bf16x2 lo (low 16 bits = first elem).
static __device__ __forceinline__ void split_bf2(float vx, float vy,
                                                 uint32_t& hi, uint32_t& lo) {
    __nv_bfloat162 h = __floats2bfloat162_rn(vx, vy);
    uint32_t u = *(uint32_t*)&h;
    float f0 = __uint_as_float(u << 16);
    float f1 = __uint_as_float(u & 0xffff0000u);
    __nv_bfloat162 l = __floats2bfloat162_rn(vx - f0, vy - f1);
    hi = u;
    lo = *(uint32_t*)&l;
}

// ---------------------------------------------------------------------------
// Fused: dtype detect (block 0) + zero counters + B-fragment pack of W.
// m16n8k16 B frag: lane -> n = nt*8 + lane/4; reg b0 = {W[n][k0+2t], W[n][k0+2t+1]},
// b1 = {W[n][k0+2t+8], W[n][k0+2t+9]}, t = lane%4, k0 = kc*16.
__global__ void k_detect_prep(const long long* __restrict__ ei,
                              const float* __restrict__ W) {
    int i = blockIdx.x * blockDim.x + threadIdx.x;
    if (i < N_NODES) { g_cnt[i] = 0; g_cur[i] = 0; }
    if (i < NFRAG) {
        int lane = i & 31;
        int frag = i >> 5;
        int nt = frag & 15;
        int kc = frag >> 4;          // 0..7
        int n = nt * 8 + (lane >> 2);
        int t = lane & 3;
        int ka = kc * 16 + 2 * t;
        int kb = ka + 8;
        uint32_t h0, l0, h1, l1;
        split_bf2(W[n * C + ka], W[n * C + ka + 1], h0, l0);
        split_bf2(W[n * C + kb], W[n * C + kb + 1], h1, l1);
        g_Wf[i] = make_uint4(h0, h1, l0, l1);
    }
    if (blockIdx.x == 0) {
        __shared__ int ok;
        if (threadIdx.x == 0) ok = 1;
        __syncthreads();
        for (int s = threadIdx.x; s < 1024; s += blockDim.x) {
            long long v = ei[s];
            if (v < 0 || v >= N_NODES) atomicExch(&ok, 0);
        }
        __syncthreads();
        if (threadIdx.x == 0) g_is64 = ok;
    }
}

// normalize edges + count degrees in one pass
__global__ void k_edges(const void* __restrict__ ei) {
    int e = blockIdx.x * blockDim.x + threadIdx.x;
    if (e >= N_EDGES) return;
    int r, c;
    if (g_is64) {
        const long long* p = (const long long*)ei;
        r = (int)p[e];
        c = (int)p[e + N_EDGES];
    } else {
        const int* p = (const int*)ei;
        r = p[e];
        c = p[e + N_EDGES];
    }
    g_row[e] = r;
    g_col[e] = c;
    if ((unsigned)r < N_NODES) atomicAdd(&g_cnt[r], 1);
}

// ---------------------------------------------------------------------------
__global__ void __launch_bounds__(256) k_scan1() {
    __shared__ int s[256];
    const int t = threadIdx.x;
    const int i = blockIdx.x * 256 + t;
    s[t] = (i < N_NODES) ? g_cnt[i] : 0;
    __syncthreads();
#pragma unroll
    for (int off = 128; off > 0; off >>= 1) {
        if (t < off) s[t] += s[t + off];
        __syncthreads();
    }
    if (t == 0) g_part[blockIdx.x] = s[0];
}

__global__ void __launch_bounds__(256) k_scan_off() {
    __shared__ int sp[256];
    __shared__ int s[256];
    const int t = threadIdx.x;

    const int pv = (t < NPART) ? g_part[t] : 0;
    sp[t] = pv;
    __syncthreads();
#pragma unroll
    for (int off = 1; off < 256; off <<= 1) {
        int u = (t >= off) ? sp[t - off] : 0;
        __syncthreads();
        sp[t] += u;
        __syncthreads();
    }
    const int blk_prefix = (blockIdx.x == 0) ? 0 : sp[blockIdx.x - 1];
    if (blockIdx.x == 0 && t == 0) g_off[N_NODES] = sp[NPART - 1];

    const int i = blockIdx.x * 256 + t;
    const int v = (i < N_NODES) ? g_cnt[i] : 0;
    s[t] = v;
    __syncthreads();
#pragma unroll
    for (int off = 1; off < 256; off <<= 1) {
        int u = (t >= off) ? s[t - off] : 0;
        __syncthreads();
        s[t] += u;
        __syncthreads();
    }
    if (i < N_NODES) {
        g_off[i] = s[t] - v + blk_prefix;
        g_dis[i] = (v > 0) ? rsqrtf((float)v) : 0.f;
    }
}

__global__ void k_fill_csr() {
    int e = blockIdx.x * blockDim.x + threadIdx.x;
    if (e >= N_EDGES) return;
    unsigned r = (unsigned)g_row[e];
    unsigned c = (unsigned)g_col[e];
    if (r >= N_NODES || c >= N_NODES) return;
    int pos = g_off[r] + atomicAdd(&g_cur[r], 1);
    g_ecol[pos] = (int)c;
}

// ---------------------------------------------------------------------------
// y = x @ W^T via mma.sync m16n8k16 3xBF16 (hi/lo split; dropped lo*lo ~ 2^-18).
// (256,2), fully unrolled; fp32 accum, fp16 store. ONE __syncthreads total.
__global__ void __launch_bounds__(256, 2) k_gemm_mma(const float* __restrict__ x) {
    __shared__ float xs[GM][132];   // pad 132: float2 A-loads conflict-light

    const int tid = threadIdx.x;
    const int wid = tid >> 5, lane = tid & 31;
    const int g = lane >> 2, t = lane & 3;
    const int mg = wid >> 2;        // 0..1  -> rows mg*32 + mt*16
    const int ng = wid & 3;         // 0..3  -> nt = ng*4 + ntl
    const int row0 = blockIdx.x * GM;

    // Load x tile (coalesced float4; zero-pad tail rows)
    for (int i = tid; i < GM * 32; i += 256) {
        int r = i >> 5, q = i & 31;
        float4 v = make_float4(0.f, 0.f, 0.f, 0.f);
        if (row0 + r < N_NODES)
            v = ((const float4*)(x + (size_t)(row0 + r) * C))[q];
        *(float4*)&xs[r][4 * q] = v;
    }
    __syncthreads();

    float4 acc[2][4];
#pragma unroll
    for (int mt = 0; mt < 2; mt++)
#pragma unroll
        for (int n = 0; n < 4; n++) acc[mt][n] = make_float4(0.f, 0.f, 0.f, 0.f);

    const uint4* wf = g_Wf + (size_t)(ng * 4) * 32 + lane;

#pragma unroll
    for (int kc = 0; kc < 8; kc++) {
        const int ka = kc * 16 + 2 * t;
        // B fragments first (independent LDG.128s -> front-batched)
        uint4 bf[4];
#pragma unroll
        for (int ntl = 0; ntl < 4; ntl++)
            bf[ntl] = __ldg(wf + (size_t)(kc * 16 + ntl) * 32);

        // A fragments for 2 m-tiles (bf16 hi/lo split on the fly)
        uint32_t ah[2][4], al[2][4];
#pragma unroll
        for (int mt = 0; mt < 2; mt++) {
            const int r0 = mg * 32 + mt * 16 + g;
            float2 p0 = *(const float2*)&xs[r0][ka];
            float2 p1 = *(const float2*)&xs[r0 + 8][ka];
            float2 p2 = *(const float2*)&xs[r0][ka + 8];
            float2 p3 = *(const float2*)&xs[r0 + 8][ka + 8];
            split_bf2(p0.x, p0.y, ah[mt][0], al[mt][0]);
            split_bf2(p1.x, p1.y, ah[mt][1], al[mt][1]);
            split_bf2(p2.x, p2.y, ah[mt][2], al[mt][2]);
            split_bf2(p3.x, p3.y, ah[mt][3], al[mt][3]);
        }
#pragma unroll
        for (int ntl = 0; ntl < 4; ntl++) {
            const uint32_t h0 = bf[ntl].x, h1 = bf[ntl].y;
            const uint32_t l0 = bf[ntl].z, l1 = bf[ntl].w;
#pragma unroll
            for (int mt = 0; mt < 2; mt++) {
                mma16(acc[mt][ntl], ah[mt], h0, h1);   // hi*hi
                mma16(acc[mt][ntl], ah[mt], l0, l1);   // hi*lo
                mma16(acc[mt][ntl], al[mt], h0, h1);   // lo*hi
            }
        }
    }

    // Epilogue: fp32 acc -> fp16; c0/c1 -> (row g, cols 2t,2t+1), c2/c3 -> row g+8
#pragma unroll
    for (int mt = 0; mt < 2; mt++) {
        const size_t gr0 = (size_t)(row0 + mg * 32 + mt * 16 + g) * C;
        const size_t gr1 = gr0 + 8 * C;
#pragma unroll
        for (int ntl = 0; ntl < 4; ntl++) {
            const int cb = (ng * 4 + ntl) * 8 + 2 * t;
            *(__half2*)&g_yh[gr0 + cb] = __floats2half2_rn(acc[mt][ntl].x, acc[mt][ntl].y);
            *(__half2*)&g_yh[gr1 + cb] = __floats2half2_rn(acc[mt][ntl].z, acc[mt][ntl].w);
        }
    }
}

// ---------------------------------------------------------------------------
// Warp per node, 2-edge unrolled; y rows read as fp16 (half L2 traffic):
// out[n] = b + dis[n] * sum_e dis[col_e] * y[col_e]
__global__ void __launch_bounds__(256) k_gather(float* __restrict__ out,
                                                const float* __restrict__ b) {
    int gtid = blockIdx.x * blockDim.x + threadIdx.x;
    int n = gtid >> 5;
    int lane = gtid & 31;
    if (n >= N_NODES) return;

    const float4 bias = __ldg(((const float4*)b) + lane);
    float ax = 0.f, ay = 0.f, az = 0.f, aw = 0.f;

    const int start = g_off[n];
    const int end = g_off[n + 1];
    const float dn = g_dis[n];

    int e = start;
    for (; e + 2 <= end; e += 2) {
        int c0 = g_ecol[e];
        int c1 = g_ecol[e + 1];
        float m0 = dn * g_dis[c0];
        float m1 = dn * g_dis[c1];
        uint2 u0 = __ldg(((const uint2*)(g_yh + (size_t)c0 * C)) + lane);
        uint2 u1 = __ldg(((const uint2*)(g_yh + (size_t)c1 * C)) + lane);
        float2 a0 = __half22float2(*(__half2*)&u0.x);
        float2 b0v = __half22float2(*(__half2*)&u0.y);
        float2 a1 = __half22float2(*(__half2*)&u1.x);
        float2 b1v = __half22float2(*(__half2*)&u1.y);
        ax += m0 * a0.x + m1 * a1.x;
        ay += m0 * a0.y + m1 * a1.y;
        az += m0 * b0v.x + m1 * b1v.x;
        aw += m0 * b0v.y + m1 * b1v.y;
    }
    if (e < end) {
        int c = g_ecol[e];
        float m = dn * g_dis[c];
        uint2 u = __ldg(((const uint2*)(g_yh + (size_t)c * C)) + lane);
        float2 a0 = __half22float2(*(__half2*)&u.x);
        float2 b0v = __half22float2(*(__half2*)&u.y);
        ax += m * a0.x;
        ay += m * a0.y;
        az += m * b0v.x;
        aw += m * b0v.y;
    }

    ((float4*)(out + (size_t)n * C))[lane] =
        make_float4(bias.x + ax, bias.y + ay, bias.z + az, bias.w + aw);
}

// ---------------------------------------------------------------------------
extern "C" void kernel_launch(void* const* d_in, const int* in_sizes, int n_in,
                              void* d_out, int out_size) {
    const float* x = (const float*)d_in[0];
    const void*  ei = d_in[1];
    const float* W = (const float*)d_in[2];
    const float* b = (const float*)d_in[3];
    float* out = (float*)d_out;

    // Fork/join: CSR chain runs on a side stream, overlapped with the GEMM.
    cudaStream_t s2;
    cudaStreamCreateWithFlags(&s2, cudaStreamNonBlocking);
    cudaEvent_t evFork, evJoin;
    cudaEventCreateWithFlags(&evFork, cudaEventDisableTiming);
    cudaEventCreateWithFlags(&evJoin, cudaEventDisableTiming);

    k_detect_prep<<<(N_NODES + 255) / 256, 256>>>((const long long*)ei, W);   // 1
    cudaEventRecord(evFork, 0);
    cudaStreamWaitEvent(s2, evFork, 0);

    k_edges<<<(N_EDGES + 255) / 256, 256, 0, s2>>>(ei);                       // 2
    k_scan1<<<NPART, 256, 0, s2>>>();                                         // 3
    k_gemm_mma<<<GBLKS, 256>>>(x);                                            // 4 (profiled)
    k_scan_off<<<NPART, 256, 0, s2>>>();                                      // 5
    k_fill_csr<<<(N_EDGES + 255) / 256, 256, 0, s2>>>();                      // 6
    cudaEventRecord(evJoin, s2);
    cudaStreamWaitEvent(0, evJoin, 0);

    const long long total = (long long)N_NODES * 32;
    k_gather<<<(int)((total + 255) / 256), 256>>>(out, b);                    // 7

    cudaEventDestroy(evFork);
    cudaEventDestroy(evJoin);
    cudaStreamDestroy(s2);
}

// round 15
// speedup vs baseline: 1.8367x; 1.0015x over previous
#include <cuda_runtime.h>
#include <cuda_fp16.h>
#include <cuda_bf16.h>
#include <cstdint>

#define N_NODES 50000
#define N_EDGES 625000
#define C 128
#define NPART ((N_NODES + 255) / 256)   // 196 scan blocks
#define GM 64                            // GEMM rows per block
#define GBLKS ((N_NODES + GM - 1) / GM)  // 782
#define PADROWS (GBLKS * GM)             // 50048
#define NFRAG (8 * 16 * 32)              // kc16 * nt * lane = 4096

// Scratch (__device__ globals; allocations are banned)
__device__ __align__(16) __half g_yh[(size_t)PADROWS * C];  // x @ W^T, fp16
__device__ __align__(16) uint4  g_Wf[NFRAG];  // B frags: (hi0,hi1,lo0,lo1) bf16x2
__device__ float g_dis[N_NODES];             // deg^-1/2
__device__ int   g_row[N_EDGES];
__device__ int   g_col[N_EDGES];
__device__ int   g_cnt[N_NODES];             // degree counts
__device__ int   g_cur[N_NODES];             // fill cursors
__device__ int   g_off[N_NODES + 1];         // CSR offsets
__device__ int   g_ecol[N_EDGES];            // CSR column (src) ids
__device__ int   g_part[NPART];              // scan partials
__device__ int   g_is64;

// ---------------------------------------------------------------------------
static __device__ __forceinline__ void mma16(float4& d, const uint32_t* a,
                                             uint32_t b0, uint32_t b1) {
    asm volatile(
        "mma.sync.aligned.m16n8k16.row.col.f32.bf16.bf16.f32 "
        "{%0,%1,%2,%3}, {%4,%5,%6,%7}, {%8,%9}, {%0,%1,%2,%3};"
        : "+f"(d.x), "+f"(d.y), "+f"(d.z), "+f"(d.w)
        : "r"(a[0]), "r"(a[1]), "r"(a[2]), "r"(a[3]), "r"(b0), "r"(b1));
}

// Split a float pair into bf16x2 hi and bf16x2 lo (low 16 bits = first elem).
static __device__ __forceinline__ void split_bf2(float vx, float vy,
                                                 uint32_t& hi, uint32_t& lo) {
    __nv_bfloat162 h = __floats2bfloat162_rn(vx, vy);
    uint32_t u = *(uint32_t*)&h;
    float f0 = __uint_as_float(u << 16);
    float f1 = __uint_as_float(u & 0xffff0000u);
    __nv_bfloat162 l = __floats2bfloat162_rn(vx - f0, vy - f1);
    hi = u;
    lo = *(uint32_t*)&l;
}

// ---------------------------------------------------------------------------
// Fused: dtype detect (block 0) + zero counters + B-fragment pack of W.
// m16n8k16 B frag: lane -> n = nt*8 + lane/4; reg b0 = {W[n][k0+2t], W[n][k0+2t+1]},
// b1 = {W[n][k0+2t+8], W[n][k0+2t+9]}, t = lane%4, k0 = kc*16.
__global__ void k_detect_prep(const long long* __restrict__ ei,
                              const float* __restrict__ W) {
    int i = blockIdx.x * blockDim.x + threadIdx.x;
    if (i < N_NODES) { g_cnt[i] = 0; g_cur[i] = 0; }
    if (i < NFRAG) {
        int lane = i & 31;
        int frag = i >> 5;
        int nt = frag & 15;
        int kc = frag >> 4;          // 0..7
        int n = nt * 8 + (lane >> 2);
        int t = lane & 3;
        int ka = kc * 16 + 2 * t;
        int kb = ka + 8;
        uint32_t h0, l0, h1, l1;
        split_bf2(W[n * C + ka], W[n * C + ka + 1], h0, l0);
        split_bf2(W[n * C + kb], W[n * C + kb + 1], h1, l1);
        g_Wf[i] = make_uint4(h0, h1, l0, l1);
    }
    if (blockIdx.x == 0) {
        __shared__ int ok;
        if (threadIdx.x == 0) ok = 1;
        __syncthreads();
        for (int s = threadIdx.x; s < 1024; s += blockDim.x) {
            long long v = ei[s];
            if (v < 0 || v >= N_NODES) atomicExch(&ok, 0);
        }
        __syncthreads();
        if (threadIdx.x == 0) g_is64 = ok;
    }
}

// normalize edges + count degrees in one pass
__global__ void k_edges(const void* __restrict__ ei) {
    int e = blockIdx.x * blockDim.x + threadIdx.x;
    if (e >= N_EDGES) return;
    int r, c;
    if (g_is64) {
        const long long* p = (const long long*)ei;
        r = (int)p[e];
        c = (int)p[e + N_EDGES];
    } else {
        const int* p = (const int*)ei;
        r = p[e];
        c = p[e + N_EDGES];
    }
    g_row[e] = r;
    g_col[e] = c;
    if ((unsigned)r < N_NODES) atomicAdd(&g_cnt[r], 1);
}

// ---------------------------------------------------------------------------
__global__ void __launch_bounds__(256) k_scan1() {
    __shared__ int s[256];
    const int t = threadIdx.x;
    const int i = blockIdx.x * 256 + t;
    s[t] = (i < N_NODES) ? g_cnt[i] : 0;
    __syncthreads();
#pragma unroll
    for (int off = 128; off > 0; off >>= 1) {
        if (t < off) s[t] += s[t + off];
        __syncthreads();
    }
    if (t == 0) g_part[blockIdx.x] = s[0];
}

__global__ void __launch_bounds__(256) k_scan_off() {
    __shared__ int sp[256];
    __shared__ int s[256];
    const int t = threadIdx.x;

    const int pv = (t < NPART) ? g_part[t] : 0;
    sp[t] = pv;
    __syncthreads();
#pragma unroll
    for (int off = 1; off < 256; off <<= 1) {
        int u = (t >= off) ? sp[t - off] : 0;
        __syncthreads();
        sp[t] += u;
        __syncthreads();
    }
    const int blk_prefix = (blockIdx.x == 0) ? 0 : sp[blockIdx.x - 1];
    if (blockIdx.x == 0 && t == 0) g_off[N_NODES] = sp[NPART - 1];

    const int i = blockIdx.x * 256 + t;
    const int v = (i < N_NODES) ? g_cnt[i] : 0;
    s[t] = v;
    __syncthreads();
#pragma unroll
    for (int off = 1; off < 256; off <<= 1) {
        int u = (t >= off) ? s[t - off] : 0;
        __syncthreads();
        s[t] += u;
        __syncthreads();
    }
    if (i < N_NODES) {
        g_off[i] = s[t] - v + blk_prefix;
        g_dis[i] = (v > 0) ? rsqrtf((float)v) : 0.f;
    }
}

__global__ void k_fill_csr() {
    int e = blockIdx.x * blockDim.x + threadIdx.x;
    if (e >= N_EDGES) return;
    unsigned r = (unsigned)g_row[e];
    unsigned c = (unsigned)g_col[e];
    if (r >= N_NODES || c >= N_NODES) return;
    int pos = g_off[r] + atomicAdd(&g_cur[r], 1);
    g_ecol[pos] = (int)c;
}

// ---------------------------------------------------------------------------
// y = x @ W^T via mma.sync m16n8k16 3xBF16. x tile pre-split to (hi,lo)
// bf16x2 at load -> mainloop is pure LDS.64 -> MMA (no cvt on critical path).
// (256,2), fully unrolled; fp32 accum, fp16 store. ONE __syncthreads total.
__global__ void __launch_bounds__(256, 2) k_gemm_mma(const float* __restrict__ x) {
    // uint2 = (hi bf16x2, lo bf16x2) for k-pair. Row stride 66*8=528B — same
    // byte-bank profile as the proven float[132] layout.
    __shared__ uint2 xhl[GM][66];

    const int tid = threadIdx.x;
    const int wid = tid >> 5, lane = tid & 31;
    const int g = lane >> 2, t = lane & 3;
    const int mg = wid >> 2;        // 0..1  -> rows mg*32 + mt*16
    const int ng = wid & 3;         // 0..3  -> nt = ng*4 + ntl
    const int row0 = blockIdx.x * GM;

    // Load x tile (coalesced float4), split hi/lo once, store packed
    for (int i = tid; i < GM * 32; i += 256) {
        int r = i >> 5, q = i & 31;
        float4 v = make_float4(0.f, 0.f, 0.f, 0.f);
        if (row0 + r < N_NODES)
            v = ((const float4*)(x + (size_t)(row0 + r) * C))[q];
        uint32_t h0, l0, h1, l1;
        split_bf2(v.x, v.y, h0, l0);
        split_bf2(v.z, v.w, h1, l1);
        xhl[r][2 * q]     = make_uint2(h0, l0);
        xhl[r][2 * q + 1] = make_uint2(h1, l1);
    }
    __syncthreads();

    float4 acc[2][4];
#pragma unroll
    for (int mt = 0; mt < 2; mt++)
#pragma unroll
        for (int n = 0; n < 4; n++) acc[mt][n] = make_float4(0.f, 0.f, 0.f, 0.f);

    const uint4* wf = g_Wf + (size_t)(ng * 4) * 32 + lane;

#pragma unroll
    for (int kc = 0; kc < 8; kc++) {
        const int kp = kc * 8 + t;   // k-pair index
        // B fragments first (independent LDG.128s -> front-batched)
        uint4 bf[4];
#pragma unroll
        for (int ntl = 0; ntl < 4; ntl++)
            bf[ntl] = __ldg(wf + (size_t)(kc * 16 + ntl) * 32);

        // A fragments: pure LDS.64, no conversion
        uint32_t ah[2][4], al[2][4];
#pragma unroll
        for (int mt = 0; mt < 2; mt++) {
            const int r0 = mg * 32 + mt * 16 + g;
            uint2 u0 = xhl[r0][kp];
            uint2 u1 = xhl[r0 + 8][kp];
            uint2 u2 = xhl[r0][kp + 4];
            uint2 u3 = xhl[r0 + 8][kp + 4];
            ah[mt][0] = u0.x; al[mt][0] = u0.y;
            ah[mt][1] = u1.x; al[mt][1] = u1.y;
            ah[mt][2] = u2.x; al[mt][2] = u2.y;
            ah[mt][3] = u3.x; al[mt][3] = u3.y;
        }
#pragma unroll
        for (int ntl = 0; ntl < 4; ntl++) {
            const uint32_t h0 = bf[ntl].x, h1 = bf[ntl].y;
            const uint32_t l0 = bf[ntl].z, l1 = bf[ntl].w;
#pragma unroll
            for (int mt = 0; mt < 2; mt++) {
                mma16(acc[mt][ntl], ah[mt], h0, h1);   // hi*hi
                mma16(acc[mt][ntl], ah[mt], l0, l1);   // hi*lo
                mma16(acc[mt][ntl], al[mt], h0, h1);   // lo*hi
            }
        }
    }

    // Epilogue: fp32 acc -> fp16; c0/c1 -> (row g, cols 2t,2t+1), c2/c3 -> row g+8
#pragma unroll
    for (int mt = 0; mt < 2; mt++) {
        const size_t gr0 = (size_t)(row0 + mg * 32 + mt * 16 + g) * C;
        const size_t gr1 = gr0 + 8 * C;
#pragma unroll
        for (int ntl = 0; ntl < 4; ntl++) {
            const int cb = (ng * 4 + ntl) * 8 + 2 * t;
            *(__half2*)&g_yh[gr0 + cb] = __floats2half2_rn(acc[mt][ntl].x, acc[mt][ntl].y);
            *(__half2*)&g_yh[gr1 + cb] = __floats2half2_rn(acc[mt][ntl].z, acc[mt][ntl].w);
        }
    }
}

// ---------------------------------------------------------------------------
// Warp per node, 2-edge unrolled; y rows read as fp16 (half L2 traffic):
// out[n] = b + dis[n] * sum_e dis[col_e] * y[col_e]
__global__ void __launch_bounds__(256) k_gather(float* __restrict__ out,
                                                const float* __restrict__ b) {
    int gtid = blockIdx.x * blockDim.x + threadIdx.x;
    int n = gtid >> 5;
    int lane = gtid & 31;
    if (n >= N_NODES) return;

    const float4 bias = __ldg(((const float4*)b) + lane);
    float ax = 0.f, ay = 0.f, az = 0.f, aw = 0.f;

    const int start = g_off[n];
    const int end = g_off[n + 1];
    const float dn = g_dis[n];

    int e = start;
    for (; e + 2 <= end; e += 2) {
        int c0 = g_ecol[e];
        int c1 = g_ecol[e + 1];
        float m0 = dn * g_dis[c0];
        float m1 = dn * g_dis[c1];
        uint2 u0 = __ldg(((const uint2*)(g_yh + (size_t)c0 * C)) + lane);
        uint2 u1 = __ldg(((const uint2*)(g_yh + (size_t)c1 * C)) + lane);
        float2 a0 = __half22float2(*(__half2*)&u0.x);
        float2 b0v = __half22float2(*(__half2*)&u0.y);
        float2 a1 = __half22float2(*(__half2*)&u1.x);
        float2 b1v = __half22float2(*(__half2*)&u1.y);
        ax += m0 * a0.x + m1 * a1.x;
        ay += m0 * a0.y + m1 * a1.y;
        az += m0 * b0v.x + m1 * b1v.x;
        aw += m0 * b0v.y + m1 * b1v.y;
    }
    if (e < end) {
        int c = g_ecol[e];
        float m = dn * g_dis[c];
        uint2 u = __ldg(((const uint2*)(g_yh + (size_t)c * C)) + lane);
        float2 a0 = __half22float2(*(__half2*)&u.x);
        float2 b0v = __half22float2(*(__half2*)&u.y);
        ax += m * a0.x;
        ay += m * a0.y;
        az += m * b0v.x;
        aw += m * b0v.y;
    }

    ((float4*)(out + (size_t)n * C))[lane] =
        make_float4(bias.x + ax, bias.y + ay, bias.z + az, bias.w + aw);
}

// ---------------------------------------------------------------------------
extern "C" void kernel_launch(void* const* d_in, const int* in_sizes, int n_in,
                              void* d_out, int out_size) {
    const float* x = (const float*)d_in[0];
    const void*  ei = d_in[1];
    const float* W = (const float*)d_in[2];
    const float* b = (const float*)d_in[3];
    float* out = (float*)d_out;

    // Fork/join: CSR chain runs on a side stream, overlapped with the GEMM.
    cudaStream_t s2;
    cudaStreamCreateWithFlags(&s2, cudaStreamNonBlocking);
    cudaEvent_t evFork, evJoin;
    cudaEventCreateWithFlags(&evFork, cudaEventDisableTiming);
    cudaEventCreateWithFlags(&evJoin, cudaEventDisableTiming);

    k_detect_prep<<<(N_NODES + 255) / 256, 256>>>((const long long*)ei, W);   // 1
    cudaEventRecord(evFork, 0);
    cudaStreamWaitEvent(s2, evFork, 0);

    k_edges<<<(N_EDGES + 255) / 256, 256, 0, s2>>>(ei);                       // 2
    k_scan1<<<NPART, 256, 0, s2>>>();                                         // 3
    k_gemm_mma<<<GBLKS, 256>>>(x);                                            // 4 (profiled)
    k_scan_off<<<NPART, 256, 0, s2>>>();                                      // 5
    k_fill_csr<<<(N_EDGES + 255) / 256, 256, 0, s2>>>();                      // 6
    cudaEventRecord(evJoin, s2);
    cudaStreamWaitEvent(0, evJoin, 0);

    const long long total = (long long)N_NODES * 32;
    k_gather<<<(int)((total + 255) / 256), 256>>>(out, b);                    // 7

    cudaEventDestroy(evFork);
    cudaEventDestroy(evJoin);
    cudaStreamDestroy(s2);
}